// round 15
// baseline (speedup 1.0000x reference)
#include <cuda_runtime.h>
#include <cstdint>

#define NN   40000
#define EE   400000
#define EP   (EE + NN)
#define HH   8
#define HC   512
#define FF   16
#define RR   40
#define KOUT 39
#define WCOL 61
#define NLOG (RR * RR * KOUT)
#define NCH  40

// ---------------- scratch (doubled: both graphs live simultaneously) --------
__device__ float g_as[2][NN * HH];
__device__ float g_ad[2][NN * HH];
__device__ int   g_deg[2][NN];
__device__ int   g_rowptr[2][NN + 1];
__device__ int   g_cursor[2][NN];
__device__ int   g_srcs[2][EP];            // dst-sorted src ids
__device__ int   g_bsum[2][NCH];
__device__ float g_va[FF * HH];            // W@att_src  (f-major: [f][h])
__device__ float g_vd[FF * HH];            // W@att_dst
__device__ float g_ragg[2][RR * HH * FF];  // route-level alpha-weighted x sums
__device__ int   g_cnt[2][RR];
__device__ float g_U[2][RR * 64];
__device__ float g_logits[NLOG];

__device__ __forceinline__ void red4(float* p, float4 v) {
    asm volatile("red.global.add.v4.f32 [%0], {%1, %2, %3, %4};"
                 :: "l"(p), "f"(v.x), "f"(v.y), "f"(v.z), "f"(v.w) : "memory");
}

// ---------------- setup: zero accumulators + precontract W with att ---------
__global__ void k_setup(const float* __restrict__ W,
                        const float* __restrict__ attS,
                        const float* __restrict__ attD) {
    int b = blockIdx.x, t = threadIdx.x;
    if (b < 40) {
        int i = b * 256 + t;
        if (i < 2 * RR * HH * FF) ((float*)g_ragg)[i] = 0.f;
        if (i < 2 * RR)           ((int*)g_cnt)[i] = 0;
    } else if (t < FF * HH) {
        int f = t >> 3, h = t & 7;
        float sa = 0.f, sd = 0.f;
        const float* wrow = W + f * HC + h * 64;
        const float* as = attS + h * 64;
        const float* ad = attD + h * 64;
        #pragma unroll
        for (int c = 0; c < 64; c++) {
            float w = wrow[c];
            sa = fmaf(w, as[c], sa);
            sd = fmaf(w, ad[c], sd);
        }
        g_va[t] = sa;
        g_vd[t] = sd;
    }
}

// ---------------- attention scores + per-graph init (both graphs) -----------
__global__ __launch_bounds__(256) void k_att(const float* __restrict__ x1,
                                             const float* __restrict__ x2,
                                             const int* __restrict__ rv1,
                                             const int* __restrict__ rv2) {
    __shared__ float sva[FF * HH], svd[FF * HH];
    int t = threadIdx.x;
    int g = blockIdx.y;
    const float* x  = g ? x2 : x1;
    const int*   rv = g ? rv2 : rv1;
    if (t < FF * HH) { sva[t] = g_va[t]; svd[t] = g_vd[t]; }
    __syncthreads();

    int n = blockIdx.x * blockDim.x + t;
    if (n >= NN) return;

    g_deg[g][n] = 1;   // self loop
    atomicAdd(&g_cnt[g][rv[n]], 1);

    const float4* x4 = (const float4*)(x + n * FF);
    float4 v0 = x4[0], v1 = x4[1], v2 = x4[2], v3 = x4[3];
    float xr[FF] = { v0.x, v0.y, v0.z, v0.w, v1.x, v1.y, v1.z, v1.w,
                     v2.x, v2.y, v2.z, v2.w, v3.x, v3.y, v3.z, v3.w };
    float as[HH], ad[HH];
    #pragma unroll
    for (int h = 0; h < HH; h++) { as[h] = 0.f; ad[h] = 0.f; }
    #pragma unroll
    for (int f = 0; f < FF; f++) {
        #pragma unroll
        for (int h = 0; h < HH; h++) {
            as[h] = fmaf(xr[f], sva[f * HH + h], as[h]);
            ad[h] = fmaf(xr[f], svd[f * HH + h], ad[h]);
        }
    }
    float4* o = (float4*)(g_as[g] + n * HH);
    o[0] = make_float4(as[0], as[1], as[2], as[3]);
    o[1] = make_float4(as[4], as[5], as[6], as[7]);
    float4* o2 = (float4*)(g_ad[g] + n * HH);
    o2[0] = make_float4(ad[0], ad[1], ad[2], ad[3]);
    o2[1] = make_float4(ad[4], ad[5], ad[6], ad[7]);
}

// ---------------- in-degree histogram (both graphs) -------------------------
__global__ void k_deg(const int* __restrict__ ei1, const int* __restrict__ ei2) {
    int i = blockIdx.x * blockDim.x + threadIdx.x;
    int g = blockIdx.y;
    const int* ei = g ? ei2 : ei1;
    if (i < EE) atomicAdd(&g_deg[g][ei[EE + i]], 1);
}

// ---------------- scan stage 1: per-chunk sums ------------------------------
__global__ void k_blocksum() {
    __shared__ int s[1024];
    int g = blockIdx.y, b = blockIdx.x, t = threadIdx.x;
    int i = b * 1024 + t;
    s[t] = (i < NN) ? g_deg[g][i] : 0;
    __syncthreads();
    for (int off = 512; off > 0; off >>= 1) {
        if (t < off) s[t] += s[t + off];
        __syncthreads();
    }
    if (t == 0) g_bsum[g][b] = s[0];
}

// ---------------- scan stage 2: per-chunk exclusive offsets -----------------
// Each block computes its own carry from g_bsum (<=39 independent loads).
__global__ void k_offsets() {
    __shared__ int s[1024];
    __shared__ int carrysh;
    int g = blockIdx.y, b = blockIdx.x, t = threadIdx.x;
    int i = b * 1024 + t;
    if (t == 0) {
        int c = 0;
        for (int k = 0; k < b; k++) c += g_bsum[g][k];
        carrysh = c;
    }
    int v = (i < NN) ? g_deg[g][i] : 0;
    s[t] = v;
    __syncthreads();
    for (int off = 1; off < 1024; off <<= 1) {
        int a = (t >= off) ? s[t - off] : 0;
        __syncthreads();
        s[t] += a;
        __syncthreads();
    }
    int carry = carrysh;
    if (i < NN) {
        int ex = carry + s[t] - v;
        g_rowptr[g][i] = ex;
        g_cursor[g][i] = ex;
    }
    if (i == NN) g_rowptr[g][NN] = carry + s[t];   // == EP
}

// ---------------- counting sort by dst (both graphs) ------------------------
__global__ void k_scatter(const int* __restrict__ ei1, const int* __restrict__ ei2) {
    int i = blockIdx.x * blockDim.x + threadIdx.x;
    if (i >= EP) return;
    int g = blockIdx.y;
    const int* ei = g ? ei2 : ei1;
    int src, dst;
    if (i < EE) { src = ei[i]; dst = ei[EE + i]; }
    else        { src = i - EE; dst = src; }
    int pos = atomicAdd(&g_cursor[g][dst], 1);
    g_srcs[g][pos] = src;
}

// ---------------- aggregation in x-domain: warp per dst (both graphs) -------
// Lanes 0..7 recompute ex = exp(leaky_relu(a_s[src][l] + a_d[dst][l])) on the
// fly. No max-shift: logits ~N(0,2); alpha = ex/denom shift-invariant.
// Lane l accumulates head l>>2, features (l&3)*4..+3 => flat offset 4*l.
__global__ __launch_bounds__(256) void k_emb(const float* __restrict__ x1,
                                             const float* __restrict__ x2,
                                             const int* __restrict__ rv1,
                                             const int* __restrict__ rv2) {
    int g = blockIdx.y;
    const float* x  = g ? x2 : x1;
    const int*   rv = g ? rv2 : rv1;
    int warp = threadIdx.x >> 5;
    int l    = threadIdx.x & 31;
    int dst  = blockIdx.x * 8 + warp;
    if (dst >= NN) return;

    const float* as  = g_as[g];
    const int*   srs = g_srcs[g];

    int start = g_rowptr[g][dst];
    int end   = g_rowptr[g][dst + 1];

    float adv = (l < HH) ? g_ad[g][dst * HH + l] : 0.f;
    float4 acc = make_float4(0.f, 0.f, 0.f, 0.f);
    float dsum = 0.f;                 // lanes 0..7: denom for head l
    int fq = l & 3;

    int j = start;
    for (; j + 3 < end; j += 4) {
        int s0 = srs[j], s1 = srs[j + 1], s2 = srs[j + 2], s3 = srs[j + 3];
        float t0 = 0.f, t1 = 0.f, t2 = 0.f, t3 = 0.f;
        if (l < HH) {
            t0 = as[s0 * HH + l] + adv;
            t1 = as[s1 * HH + l] + adv;
            t2 = as[s2 * HH + l] + adv;
            t3 = as[s3 * HH + l] + adv;
        }
        t0 = t0 > 0.f ? t0 : 0.2f * t0;
        t1 = t1 > 0.f ? t1 : 0.2f * t1;
        t2 = t2 > 0.f ? t2 : 0.2f * t2;
        t3 = t3 > 0.f ? t3 : 0.2f * t3;
        float e0 = __expf(t0), e1 = __expf(t1), e2 = __expf(t2), e3 = __expf(t3);
        if (l >= HH) { e0 = e1 = e2 = e3 = 0.f; }
        dsum += (e0 + e1) + (e2 + e3);
        float ea0 = __shfl_sync(0xffffffffu, e0, l >> 2);
        float ea1 = __shfl_sync(0xffffffffu, e1, l >> 2);
        float ea2 = __shfl_sync(0xffffffffu, e2, l >> 2);
        float ea3 = __shfl_sync(0xffffffffu, e3, l >> 2);
        float4 xv0 = ((const float4*)(x + s0 * FF))[fq];
        float4 xv1 = ((const float4*)(x + s1 * FF))[fq];
        float4 xv2 = ((const float4*)(x + s2 * FF))[fq];
        float4 xv3 = ((const float4*)(x + s3 * FF))[fq];
        acc.x = fmaf(ea0, xv0.x, acc.x); acc.y = fmaf(ea0, xv0.y, acc.y);
        acc.z = fmaf(ea0, xv0.z, acc.z); acc.w = fmaf(ea0, xv0.w, acc.w);
        acc.x = fmaf(ea1, xv1.x, acc.x); acc.y = fmaf(ea1, xv1.y, acc.y);
        acc.z = fmaf(ea1, xv1.z, acc.z); acc.w = fmaf(ea1, xv1.w, acc.w);
        acc.x = fmaf(ea2, xv2.x, acc.x); acc.y = fmaf(ea2, xv2.y, acc.y);
        acc.z = fmaf(ea2, xv2.z, acc.z); acc.w = fmaf(ea2, xv2.w, acc.w);
        acc.x = fmaf(ea3, xv3.x, acc.x); acc.y = fmaf(ea3, xv3.y, acc.y);
        acc.z = fmaf(ea3, xv3.z, acc.z); acc.w = fmaf(ea3, xv3.w, acc.w);
    }
    for (; j < end; j++) {
        int s0 = srs[j];
        float t0 = 0.f;
        if (l < HH) t0 = as[s0 * HH + l] + adv;
        t0 = t0 > 0.f ? t0 : 0.2f * t0;
        float e0 = __expf(t0);
        if (l >= HH) e0 = 0.f;
        dsum += e0;
        float ea0 = __shfl_sync(0xffffffffu, e0, l >> 2);
        float4 xv0 = ((const float4*)(x + s0 * FF))[fq];
        acc.x = fmaf(ea0, xv0.x, acc.x); acc.y = fmaf(ea0, xv0.y, acc.y);
        acc.z = fmaf(ea0, xv0.z, acc.z); acc.w = fmaf(ea0, xv0.w, acc.w);
    }

    float dinv = 1.f / dsum;                         // lanes 0..7 valid
    float invh = __shfl_sync(0xffffffffu, dinv, l >> 2);
    acc.x *= invh; acc.y *= invh; acc.z *= invh; acc.w *= invh;

    int route = rv[dst];
    red4(&g_ragg[g][route * (HH * FF) + 4 * l], acc);
}

// ---------------- per-route: apply W, bias, then W_head slice ---------------
__global__ void k_U(const float* __restrict__ W, const float* __restrict__ bias,
                    const float* __restrict__ Whead) {
    __shared__ float sA[HC];
    __shared__ float sR[HH * FF];
    int b = blockIdx.x;
    int which = b & 1;
    int r     = b >> 1;
    int t = threadIdx.x;
    float cnt = (float)g_cnt[which][r];
    if (t < HH * FF) sR[t] = g_ragg[which][r * (HH * FF) + t];
    __syncthreads();
    for (int c = t; c < HC; c += blockDim.x) {
        int h = c >> 6;
        float acc = cnt * bias[c];
        #pragma unroll
        for (int f = 0; f < FF; f++)
            acc = fmaf(sR[h * FF + f], W[f * HC + c], acc);
        sA[c] = acc;
    }
    __syncthreads();
    if (t < KOUT) {
        float acc = 0.f;
        for (int c = 0; c < HC; c++)
            acc = fmaf(sA[c], Whead[(size_t)(which * HC + c) * WCOL + t], acc);
        g_U[which][r * 64 + t] = acc;
    }
}

// ---------------- fused logits + global softmax -----------------------------
__global__ void k_softmax(const float* __restrict__ bh, float* __restrict__ out) {
    __shared__ float s[1024];
    __shared__ float gm_sh, gs_sh;
    int t = threadIdx.x;

    float m = -1e30f;
    for (int i = t; i < NLOG; i += 1024) {
        int k  = i % KOUT;
        int r2 = (i / KOUT) % RR;
        int r1 = i / (KOUT * RR);
        float v = g_U[0][r1 * 64 + k] + g_U[1][r2 * 64 + k] + bh[k];
        g_logits[i] = v;
        m = fmaxf(m, v);
    }
    s[t] = m; __syncthreads();
    for (int off = 512; off > 0; off >>= 1) {
        if (t < off) s[t] = fmaxf(s[t], s[t + off]);
        __syncthreads();
    }
    if (t == 0) gm_sh = s[0];
    __syncthreads();
    float gm = gm_sh;
    __syncthreads();

    float sum = 0.f;
    for (int i = t; i < NLOG; i += 1024) sum += expf(g_logits[i] - gm);
    s[t] = sum; __syncthreads();
    for (int off = 512; off > 0; off >>= 1) {
        if (t < off) s[t] += s[t + off];
        __syncthreads();
    }
    if (t == 0) gs_sh = s[0];
    __syncthreads();
    float inv = 1.f / gs_sh;

    for (int i = t; i < NLOG; i += 1024)
        out[i] = expf(g_logits[i] - gm) * inv;
}

// ---------------- launch -----------------------------------------------------
extern "C" void kernel_launch(void* const* d_in, const int* in_sizes, int n_in,
                              void* d_out, int out_size) {
    const float* x1   = (const float*)d_in[0];
    const int*   ei1  = (const int*)  d_in[1];
    const int*   rv1  = (const int*)  d_in[3];
    const float* x2   = (const float*)d_in[5];
    const int*   ei2  = (const int*)  d_in[6];
    const int*   rv2  = (const int*)  d_in[8];
    const float* Wg   = (const float*)d_in[10];
    const float* atS  = (const float*)d_in[11];
    const float* atD  = (const float*)d_in[12];
    const float* bg   = (const float*)d_in[13];
    const float* Wh   = (const float*)d_in[14];
    const float* bh   = (const float*)d_in[15];
    float* out = (float*)d_out;

    const int TB = 256;
    const int GN   = (NN + TB - 1) / TB;
    const int GE   = (EE + TB - 1) / TB;
    const int GEP  = (EP + TB - 1) / TB;
    const int GEMB = (NN + 7) / 8;

    k_setup<<<41, TB>>>(Wg, atS, atD);
    k_att<<<dim3(GN, 2), TB>>>(x1, x2, rv1, rv2);
    k_deg<<<dim3(GE, 2), TB>>>(ei1, ei2);
    k_blocksum<<<dim3(NCH, 2), 1024>>>();
    k_offsets<<<dim3(NCH, 2), 1024>>>();
    k_scatter<<<dim3(GEP, 2), TB>>>(ei1, ei2);
    k_emb<<<dim3(GEMB, 2), TB>>>(x1, x2, rv1, rv2);
    k_U<<<2 * RR, 128>>>(Wg, bg, Wh);
    k_softmax<<<1, 1024>>>(bh, out);
    (void)in_sizes; (void)n_in; (void)out_size;
}